// round 1
// baseline (speedup 1.0000x reference)
#include <cuda_runtime.h>

#define C_DIM   128
#define EPSF    1e-5f
#define MAXNZ   8      // max nonzeros per prior column (actual: 2)
#define MAXREG  512    // max regularizer entries (actual: 112)
#define TPB     256
#define WPB     (TPB/32)
#define NBLK    296

// ---------------- device scratch (no allocations allowed) ----------------
__device__ int   g_col_cnt[C_DIM];
__device__ int   g_col_idx[C_DIM][MAXNZ];
__device__ float g_col_val[C_DIM][MAXNZ];
__device__ int   g_nreg;
__device__ int   g_reg_ch[MAXREG];
__device__ int   g_reg_p[MAXREG];
__device__ float g_reg_coef[MAXREG];
__device__ float g_partial[4096];

// ---------------- setup: extract sparsity generically from inputs --------
__global__ void setup_kernel(const float* __restrict__ prior_me,
                             const float* __restrict__ prior_ms, int B) {
    int t = threadIdx.x;          // 128 threads
    __shared__ float s_rs[C_DIM];
    __shared__ int   s_cnt[C_DIM];
    __shared__ int   s_off[C_DIM];
    __shared__ float s_nnz;

    if (t < C_DIM) {
        // column-sparse complement of prior_me:  comp = 1 - prior_me
        int cnt = 0;
        for (int r = 0; r < C_DIM; ++r) {
            float comp = 1.0f - prior_me[r * C_DIM + t];
            if (comp != 0.0f && cnt < MAXNZ) {
                g_col_idx[t][cnt] = r;
                g_col_val[t][cnt] = comp;
                cnt++;
            }
        }
        g_col_cnt[t] = cnt;
        // row stats of prior_ms
        float rs = 0.f; int c2 = 0;
        for (int d = 0; d < C_DIM; ++d) {
            float v = prior_ms[t * C_DIM + d];
            rs += v;
            if (v != 0.0f) c2++;
        }
        s_rs[t]  = rs;
        s_cnt[t] = (rs > 0.f) ? c2 : 0;
    }
    __syncthreads();
    if (t == 0) {
        int nnz_rows = 0, off = 0;
        for (int r = 0; r < C_DIM; ++r) {
            if (s_rs[r] > 0.f) nnz_rows++;
            s_off[r] = off;
            off += s_cnt[r];
        }
        g_nreg = (off < MAXREG) ? off : MAXREG;
        s_nnz  = (float)nnz_rows;
    }
    __syncthreads();
    if (t < C_DIM && s_rs[t] > 0.f) {
        int off = s_off[t];
        float coef_base = 4.0f / ((float)B * s_rs[t] * s_nnz);  // SYMBIOTIC=4 folded
        for (int d = 0; d < C_DIM; ++d) {
            float v = prior_ms[t * C_DIM + d];
            if (v != 0.0f && off < MAXREG) {
                g_reg_ch[off]   = d;
                g_reg_p[off]    = t;
                g_reg_coef[off] = coef_base * v;
                off++;
            }
        }
    }
}

// ---------------- main kernel: one warp per row, 4 classes/lane ----------
__global__ void __launch_bounds__(TPB)
main_kernel(const float* __restrict__ logits,
            const float* __restrict__ target,
            const float* __restrict__ weight,
            const float* __restrict__ v1sg, const float* __restrict__ v2sg,
            const float* __restrict__ v1sm, const float* __restrict__ v2sm,
            int B) {
    __shared__ float sh_w[C_DIM];
    __shared__ float sh_sig[3][C_DIM];
    __shared__ float sh_sm[3][C_DIM];
    __shared__ float sh_ev[WPB][C_DIM];
    __shared__ float sh_a[WPB][C_DIM];
    __shared__ int   s_col_cnt[C_DIM];
    __shared__ int   s_col_idx[C_DIM][MAXNZ];
    __shared__ float s_col_val[C_DIM][MAXNZ];
    __shared__ int   s_reg_ch[MAXREG];
    __shared__ int   s_reg_p[MAXREG];
    __shared__ float s_reg_coef[MAXREG];
    __shared__ float sh_red[TPB];

    const int tid = threadIdx.x;
    if (tid < C_DIM) {
        sh_w[tid] = weight[tid];
        float a1 = v1sg[tid], a2 = v2sg[tid];
        sh_sig[0][tid] = 0.f; sh_sig[1][tid] = a1; sh_sig[2][tid] = a1 - a2;
        float m1 = v1sm[tid], m2 = v2sm[tid];
        sh_sm[0][tid] = 0.f; sh_sm[1][tid] = m1; sh_sm[2][tid] = m1 - m2;
        s_col_cnt[tid] = g_col_cnt[tid];
        #pragma unroll
        for (int k = 0; k < MAXNZ; ++k) {
            s_col_idx[tid][k] = g_col_idx[tid][k];
            s_col_val[tid][k] = g_col_val[tid][k];
        }
    }
    const int nreg = g_nreg;
    for (int k = tid; k < nreg; k += TPB) {
        s_reg_ch[k]   = g_reg_ch[k];
        s_reg_p[k]    = g_reg_p[k];
        s_reg_coef[k] = g_reg_coef[k];
    }
    __syncthreads();

    const int lane  = tid & 31;
    const int w     = tid >> 5;
    const int gwarp = blockIdx.x * WPB + w;
    const int nwarps = gridDim.x * WPB;

    const float LOGEPS = -11.512925465f;     // logf(1e-5)
    const float LOG1ME = -1.0000050e-5f;     // logf(1 - 1e-5)

    float acc_bce = 0.f, acc_reg = 0.f;

    for (int b = gwarp; b < B; b += nwarps) {
        const float* trow = target + (size_t)b * C_DIM;
        float t4[4];
        #pragma unroll
        for (int i = 0; i < 4; ++i) t4[i] = trow[lane + 32 * i];

        // ---------- sigmoid experts 0..5 ----------
        #pragma unroll
        for (int e = 0; e < 6; ++e) {
            const float* xr = logits + ((size_t)e * B + b) * C_DIM;
            const int si = (e >= 3) ? (e - 3) : e;
            float areg[4];
            #pragma unroll
            for (int i = 0; i < 4; ++i) {
                const int c = lane + 32 * i;
                float z  = xr[c] - sh_sig[si][c];
                float ex = __expf(-z);
                float sp = __logf(1.f + ex);                 // softplus(-z)
                float la  = fminf(fmaxf(-sp,       LOGEPS), LOG1ME);
                float l1a = fminf(fmaxf(-(sp + z), LOGEPS), LOG1ME);
                float t = t4[i];
                acc_bce -= sh_w[c] * (t * la + (1.f - t) * l1a);
                if (e >= 3) {
                    float a = __frcp_rn(1.f + ex);           // sigmoid(z)
                    areg[i] = fminf(fmaxf(a, EPSF), 1.f - EPSF);
                }
            }
            if (e >= 3) {
                __syncwarp();
                #pragma unroll
                for (int i = 0; i < 4; ++i) sh_a[w][lane + 32 * i] = areg[i];
                __syncwarp();
                for (int k = lane; k < nreg; k += 32) {
                    float d = sh_a[w][s_reg_ch[k]] - sh_a[w][s_reg_p[k]];
                    acc_reg += s_reg_coef[k] * __logf(1.f + __expf(d));
                }
            }
        }

        // ---------- local-softmax experts 6..11 ----------
        #pragma unroll
        for (int j = 0; j < 6; ++j) {
            const float* xr = logits + ((size_t)(6 + j) * B + b) * C_DIM;
            const int si = (j >= 3) ? (j - 3) : j;
            float ev[4], y[4];
            float s = 0.f;
            #pragma unroll
            for (int i = 0; i < 4; ++i) {
                const int c = lane + 32 * i;
                y[i]  = xr[c] + sh_sm[si][c];
                ev[i] = __expf(y[i]);
                s += ev[i];
            }
            #pragma unroll
            for (int o = 16; o > 0; o >>= 1) s += __shfl_xor_sync(0xffffffffu, s, o);
            __syncwarp();   // prior readers of sh_ev done
            #pragma unroll
            for (int i = 0; i < 4; ++i) sh_ev[w][lane + 32 * i] = ev[i];
            __syncwarp();
            float areg[4];
            #pragma unroll
            for (int i = 0; i < 4; ++i) {
                const int c = lane + 32 * i;
                float corr = 0.f;
                const int cnt = s_col_cnt[c];
                for (int k = 0; k < cnt; ++k)
                    corr += sh_ev[w][s_col_idx[c][k]] * s_col_val[c][k];
                // denom_total = S - corr + ev + EPS ; 1-a numerator = S - corr + EPS
                float dm = s - corr + EPSF;
                float dt = dm + ev[i];
                float L  = __logf(dt);
                float la  = fminf(fmaxf(y[i] - L,        LOGEPS), LOG1ME);
                float l1a = fminf(fmaxf(__logf(dm) - L,  LOGEPS), LOG1ME);
                float t = t4[i];
                acc_bce -= sh_w[c] * (t * la + (1.f - t) * l1a);
                if (j >= 3) {
                    float a = ev[i] * __frcp_rn(dt);
                    areg[i] = fminf(fmaxf(a, EPSF), 1.f - EPSF);
                }
            }
            if (j >= 3) {
                __syncwarp();
                #pragma unroll
                for (int i = 0; i < 4; ++i) sh_a[w][lane + 32 * i] = areg[i];
                __syncwarp();
                for (int k = lane; k < nreg; k += 32) {
                    float d = sh_a[w][s_reg_ch[k]] - sh_a[w][s_reg_p[k]];
                    acc_reg += s_reg_coef[k] * __logf(1.f + __expf(d));
                }
            }
        }
    }

    float tot = acc_bce / ((float)B * (float)C_DIM) + acc_reg;
    sh_red[tid] = tot;
    __syncthreads();
    for (int st = TPB / 2; st > 0; st >>= 1) {
        if (tid < st) sh_red[tid] += sh_red[tid + st];
        __syncthreads();
    }
    if (tid == 0) g_partial[blockIdx.x] = sh_red[0];
}

// ---------------- final reduce (fp64 for stability) ----------------------
__global__ void reduce_kernel(float* __restrict__ out, int n) {
    __shared__ double sred[256];
    double s = 0.0;
    for (int i = threadIdx.x; i < n; i += 256) s += (double)g_partial[i];
    sred[threadIdx.x] = s;
    __syncthreads();
    for (int st = 128; st > 0; st >>= 1) {
        if (threadIdx.x < st) sred[threadIdx.x] += sred[threadIdx.x + st];
        __syncthreads();
    }
    if (threadIdx.x == 0) out[0] = (float)sred[0];
}

// ---------------- launch ----------------------
extern "C" void kernel_launch(void* const* d_in, const int* in_sizes, int n_in,
                              void* d_out, int out_size) {
    const float* logits   = (const float*)d_in[0];
    const float* target   = (const float*)d_in[1];
    const float* weight   = (const float*)d_in[2];
    const float* prior_me = (const float*)d_in[3];
    const float* prior_ms = (const float*)d_in[4];
    const float* v1sg     = (const float*)d_in[5];
    const float* v2sg     = (const float*)d_in[6];
    const float* v1sm     = (const float*)d_in[7];
    const float* v2sm     = (const float*)d_in[8];

    const int B = in_sizes[1] / C_DIM;   // target is [B, C]

    setup_kernel<<<1, 128>>>(prior_me, prior_ms, B);
    main_kernel<<<NBLK, TPB>>>(logits, target, weight, v1sg, v2sg, v1sm, v2sm, B);
    reduce_kernel<<<1, 256>>>((float*)d_out, NBLK);
}

// round 2
// speedup vs baseline: 1.5105x; 1.5105x over previous
#include <cuda_runtime.h>

#define C_DIM   128
#define EPSF    1e-5f
#define MAXNZ   8      // max nonzeros per prior column (actual: 2)
#define MAXREG  512    // max regularizer entries (actual: 112)
#define TPB     256
#define WPB     (TPB/32)
#define NBLK    592    // 4 CTAs/SM * 148 SMs

// ---------------- device scratch (no allocations allowed) ----------------
// column-sparse complement of prior_me, PERMUTED layout: [k][(c&3)*32 + (c>>2)]
__device__ int   g_ci[MAXNZ][C_DIM];
__device__ float g_cv[MAXNZ][C_DIM];
__device__ int   g_colmax;
__device__ int   g_nreg;
__device__ int   g_reg_cp[MAXREG];    // child | parent<<16
__device__ float g_reg_co[MAXREG];
__device__ float g_partial[4096];

// ---------------- setup: extract sparsity generically (coalesced) --------
__global__ void setup_kernel(const float* __restrict__ prior_me,
                             const float* __restrict__ prior_ms, int B) {
    __shared__ float tile[C_DIM][33];    // 16.9 KB, pad kills conflicts
    __shared__ float s_rs[C_DIM];
    __shared__ int   s_cnt[C_DIM];
    __shared__ int   s_off[C_DIM];
    __shared__ float s_nnzf;
    __shared__ int   s_cmax;

    const int t = threadIdx.x;           // 256 threads
    if (t == 0) s_cmax = 0;
    __syncthreads();

    // ---- prior_me columns: thread t owns column t (loads coalesced in t)
    if (t < C_DIM) {
        const int pc = (t & 3) * 32 + (t >> 2);   // permuted slot
        int cnt = 0;
        #pragma unroll 4
        for (int r = 0; r < C_DIM; ++r) {
            float comp = 1.0f - prior_me[r * C_DIM + t];
            if (comp != 0.0f && cnt < MAXNZ) {
                g_ci[cnt][pc] = r;
                g_cv[cnt][pc] = comp;
                cnt++;
            }
        }
        for (int k = cnt; k < MAXNZ; ++k) { g_ci[k][pc] = 0; g_cv[k][pc] = 0.f; }
        atomicMax_block(&s_cmax, cnt);
    }

    // ---- prior_ms row stats via coalesced shared tiles (4 x 128x32)
    float rs = 0.f; int cnt2 = 0;
    int   loc_ch[16]; float loc_val[16];
    for (int c0 = 0; c0 < C_DIM; c0 += 32) {
        __syncthreads();
        for (int i = t; i < C_DIM * 32; i += TPB) {
            int r = i >> 5, c = i & 31;
            tile[r][c] = prior_ms[r * C_DIM + c0 + c];
        }
        __syncthreads();
        if (t < C_DIM) {
            #pragma unroll 8
            for (int c = 0; c < 32; ++c) {
                float v = tile[t][c];
                rs += v;
                if (v != 0.0f && cnt2 < 16) { loc_ch[cnt2] = c0 + c; loc_val[cnt2] = v; cnt2++; }
            }
        }
    }
    __syncthreads();
    if (t < C_DIM) { s_rs[t] = rs; s_cnt[t] = (rs > 0.f) ? cnt2 : 0; }
    __syncthreads();
    if (t == 0) {
        int off = 0, nnzrows = 0;
        for (int r = 0; r < C_DIM; ++r) {
            s_off[r] = off;
            off += s_cnt[r];
            if (s_rs[r] > 0.f) nnzrows++;
        }
        g_nreg   = (off < MAXREG) ? off : MAXREG;
        g_colmax = s_cmax;
        s_nnzf   = (float)nnzrows;
    }
    __syncthreads();
    if (t < C_DIM && s_rs[t] > 0.f) {
        float coef = 4.0f / ((float)B * s_rs[t] * s_nnzf);   // SYMBIOTIC folded
        int off = s_off[t];
        for (int k = 0; k < cnt2 && off < MAXREG; ++k, ++off) {
            g_reg_cp[off] = loc_ch[k] | (t << 16);
            g_reg_co[off] = coef * loc_val[k];
        }
    }
}

// ---------------- main kernel: warp per row, float4 per lane -------------
__global__ void __launch_bounds__(TPB, 4)
main_kernel(const float* __restrict__ logits,
            const float* __restrict__ target,
            const float* __restrict__ weight,
            const float* __restrict__ v1sg, const float* __restrict__ v2sg,
            const float* __restrict__ v1sm, const float* __restrict__ v2sm,
            int B) {
    __shared__ float sh_w[C_DIM];              // weight / (B*C)
    __shared__ float sh_sig[3][C_DIM];
    __shared__ float sh_sm[3][C_DIM];
    __shared__ float sh_ev[WPB][C_DIM];
    __shared__ float sh_a[WPB][C_DIM];
    __shared__ int   s_ci[MAXNZ][C_DIM];       // permuted [k][j*32+l]
    __shared__ float s_cv[MAXNZ][C_DIM];
    __shared__ int   s_rcp[MAXREG];
    __shared__ float s_rco[MAXREG];
    __shared__ float sh_red[TPB];

    const int tid = threadIdx.x;
    const float invBC = 1.0f / ((float)B * (float)C_DIM);
    if (tid < C_DIM) {
        sh_w[tid] = weight[tid] * invBC;
        float a1 = v1sg[tid], a2 = v2sg[tid];
        sh_sig[0][tid] = 0.f; sh_sig[1][tid] = a1; sh_sig[2][tid] = a1 - a2;
        float m1 = v1sm[tid], m2 = v2sm[tid];
        sh_sm[0][tid] = 0.f; sh_sm[1][tid] = m1; sh_sm[2][tid] = m1 - m2;
        #pragma unroll
        for (int k = 0; k < MAXNZ; ++k) {
            s_ci[k][tid] = g_ci[k][tid];
            s_cv[k][tid] = g_cv[k][tid];
        }
    }
    const int nreg   = g_nreg;
    const int colmax = g_colmax;
    for (int k = tid; k < nreg; k += TPB) {
        s_rcp[k] = g_reg_cp[k];
        s_rco[k] = g_reg_co[k];
    }
    __syncthreads();

    const int lane   = tid & 31;
    const int w      = tid >> 5;
    const int gwarp  = blockIdx.x * WPB + w;
    const int nwarps = gridDim.x * WPB;

    const float LOGEPS = -11.512925465f;     // logf(1e-5)
    const float LOG1ME = -1.0000050e-5f;     // logf(1 - 1e-5)

    float acc_bce = 0.f, acc_reg = 0.f;

    // per-lane constants (c = 4*lane + j)
    const float4 w4 = ((const float4*)sh_w)[lane];
    float wj[4] = {w4.x, w4.y, w4.z, w4.w};

    for (int b = gwarp; b < B; b += nwarps) {
        const float4 tv = ((const float4*)(target + (size_t)b * C_DIM))[lane];
        float tj[4] = {tv.x, tv.y, tv.z, tv.w};

        // ---------- sigmoid experts 0..5 ----------
        #pragma unroll
        for (int e = 0; e < 6; ++e) {
            const float4 x = ((const float4*)(logits + ((size_t)e * B + b) * C_DIM))[lane];
            const int si = (e >= 3) ? (e - 3) : e;
            const float4 sv = ((const float4*)sh_sig[si])[lane];
            float xj[4] = {x.x, x.y, x.z, x.w};
            float sj[4] = {sv.x, sv.y, sv.z, sv.w};
            float areg[4];
            #pragma unroll
            for (int i = 0; i < 4; ++i) {
                float z  = xj[i] - sj[i];
                float ex = __expf(-z);
                float sp = __logf(1.f + ex);                 // softplus(-z)
                float la  = fminf(fmaxf(-sp,       LOGEPS), LOG1ME);
                float l1a = fminf(fmaxf(-(sp + z), LOGEPS), LOG1ME);
                acc_bce -= wj[i] * fmaf(tj[i], la - l1a, l1a);
                if (e >= 3) {
                    float a = __frcp_rn(1.f + ex);           // sigmoid(z)
                    areg[i] = fminf(fmaxf(a, EPSF), 1.f - EPSF);
                }
            }
            if (e >= 3) {
                __syncwarp();
                ((float4*)sh_a[w])[lane] = make_float4(areg[0], areg[1], areg[2], areg[3]);
                __syncwarp();
                for (int k = lane; k < nreg; k += 32) {
                    int cp = s_rcp[k];
                    float d = sh_a[w][cp & 0xffff] - sh_a[w][cp >> 16];
                    acc_reg = fmaf(s_rco[k], __logf(1.f + __expf(d)), acc_reg);
                }
            }
        }

        // ---------- local-softmax experts 6..11 ----------
        #pragma unroll
        for (int j = 0; j < 6; ++j) {
            const float4 x = ((const float4*)(logits + ((size_t)(6 + j) * B + b) * C_DIM))[lane];
            const int si = (j >= 3) ? (j - 3) : j;
            const float4 sv = ((const float4*)sh_sm[si])[lane];
            float y[4]  = {x.x + sv.x, x.y + sv.y, x.z + sv.z, x.w + sv.w};
            float ev[4];
            float s = 0.f;
            #pragma unroll
            for (int i = 0; i < 4; ++i) { ev[i] = __expf(y[i]); s += ev[i]; }
            #pragma unroll
            for (int o = 16; o > 0; o >>= 1) s += __shfl_xor_sync(0xffffffffu, s, o);
            __syncwarp();
            ((float4*)sh_ev[w])[lane] = make_float4(ev[0], ev[1], ev[2], ev[3]);
            __syncwarp();
            float areg[4];
            #pragma unroll
            for (int i = 0; i < 4; ++i) {
                const int c = 4 * lane + i;
                float corr = 0.f;
                for (int k = 0; k < colmax; ++k) {
                    int   idx = s_ci[k][i * 32 + lane];      // conflict-free
                    float v   = s_cv[k][i * 32 + lane];
                    float e2  = (idx == c) ? ev[i] : sh_ev[w][idx];
                    corr = fmaf(v, e2, corr);
                }
                float dm = s - corr + EPSF;                  // (1-a) numerator
                float dt = dm + ev[i];                       // total denom
                float L  = __logf(dt);
                float la  = fminf(fmaxf(y[i] - L,        LOGEPS), LOG1ME);
                float l1a = fminf(fmaxf(__logf(dm) - L,  LOGEPS), LOG1ME);
                acc_bce -= wj[i] * fmaf(tj[i], la - l1a, l1a);
                if (j >= 3) {
                    float a = ev[i] * __frcp_rn(dt);
                    areg[i] = fminf(fmaxf(a, EPSF), 1.f - EPSF);
                }
            }
            if (j >= 3) {
                __syncwarp();
                ((float4*)sh_a[w])[lane] = make_float4(areg[0], areg[1], areg[2], areg[3]);
                __syncwarp();
                for (int k = lane; k < nreg; k += 32) {
                    int cp = s_rcp[k];
                    float d = sh_a[w][cp & 0xffff] - sh_a[w][cp >> 16];
                    acc_reg = fmaf(s_rco[k], __logf(1.f + __expf(d)), acc_reg);
                }
            }
        }
    }

    sh_red[tid] = acc_bce + acc_reg;
    __syncthreads();
    for (int st = TPB / 2; st > 0; st >>= 1) {
        if (tid < st) sh_red[tid] += sh_red[tid + st];
        __syncthreads();
    }
    if (tid == 0) g_partial[blockIdx.x] = sh_red[0];
}

// ---------------- final reduce (fp64 for stability) ----------------------
__global__ void reduce_kernel(float* __restrict__ out, int n) {
    __shared__ double sred[256];
    double s = 0.0;
    for (int i = threadIdx.x; i < n; i += 256) s += (double)g_partial[i];
    sred[threadIdx.x] = s;
    __syncthreads();
    for (int st = 128; st > 0; st >>= 1) {
        if (threadIdx.x < st) sred[threadIdx.x] += sred[threadIdx.x + st];
        __syncthreads();
    }
    if (threadIdx.x == 0) out[0] = (float)sred[0];
}

// ---------------- launch ----------------------
extern "C" void kernel_launch(void* const* d_in, const int* in_sizes, int n_in,
                              void* d_out, int out_size) {
    const float* logits   = (const float*)d_in[0];
    const float* target   = (const float*)d_in[1];
    const float* weight   = (const float*)d_in[2];
    const float* prior_me = (const float*)d_in[3];
    const float* prior_ms = (const float*)d_in[4];
    const float* v1sg     = (const float*)d_in[5];
    const float* v2sg     = (const float*)d_in[6];
    const float* v1sm     = (const float*)d_in[7];
    const float* v2sm     = (const float*)d_in[8];

    const int B = in_sizes[1] / C_DIM;   // target is [B, C]

    setup_kernel<<<1, TPB>>>(prior_me, prior_ms, B);
    main_kernel<<<NBLK, TPB>>>(logits, target, weight, v1sg, v2sg, v1sm, v2sm, B);
    reduce_kernel<<<1, 256>>>((float*)d_out, NBLK);
}

// round 3
// speedup vs baseline: 2.0536x; 1.3595x over previous
#include <cuda_runtime.h>

#define C_DIM   128
#define EPSF    1e-5f
#define MAXNZ   8      // max nonzeros per prior column (actual: 2)
#define MAXREG  512    // max regularizer entries (actual: 112)
#define TPB     256
#define WPB     (TPB/32)
#define NBLK    592    // 4 CTAs/SM * 148 SMs
#define LOG2E   1.4426950408889634f
#define LN2F    0.6931471805599453f

// ---------------- device scratch (no allocations allowed) ----------------
// column-sparse complement of prior_me, PERMUTED layout: [k][(c&3)*32 + (c>>2)]
__device__ int   g_ci[MAXNZ][C_DIM];
__device__ float g_cv[MAXNZ][C_DIM];
__device__ int   g_colmax;
__device__ int   g_nreg;
__device__ float g_scale_reg;         // SYMBIOTIC * ln2 / n_nz
__device__ int   g_reg_cp[MAXREG];    // child | parent<<16
__device__ float g_reg_co[MAXREG];    // val / (B * row_sum)
__device__ float g_partial[4096];

// ---------------- setup: fully parallel sparse extraction ----------------
// 1 block x 1024 threads; order of appended entries is irrelevant (sums commute)
__global__ void __launch_bounds__(1024)
setup_kernel(const float* __restrict__ prior_me,
             const float* __restrict__ prior_ms, int B) {
    __shared__ int   s_ccnt[C_DIM];
    __shared__ float s_rs8[C_DIM][8];
    __shared__ int   s_nreg, s_nnz, s_cmax;

    const int t = threadIdx.x;
    if (t < C_DIM) {
        s_ccnt[t] = 0;
        #pragma unroll
        for (int k = 0; k < MAXNZ; ++k) { g_ci[k][t] = 0; g_cv[k][t] = 0.f; }
    }
    if (t == 0) { s_nreg = 0; s_nnz = 0; s_cmax = 0; }
    __syncthreads();

    // ---- phase A: columns of comp = 1 - prior_me (8 row-segments x 128 cols)
    {
        const int col  = t & 127;
        const int rseg = t >> 7;               // 0..7, 16 rows each
        const int pc   = (col & 3) * 32 + (col >> 2);
        float v[16];
        #pragma unroll
        for (int i = 0; i < 16; ++i)
            v[i] = 1.0f - prior_me[(rseg * 16 + i) * C_DIM + col];
        #pragma unroll
        for (int i = 0; i < 16; ++i) {
            if (v[i] != 0.0f) {
                int slot = atomicAdd(&s_ccnt[col], 1);
                if (slot < MAXNZ) {
                    g_ci[slot][pc] = rseg * 16 + i;
                    g_cv[slot][pc] = v[i];
                }
            }
        }
    }

    // ---- phase B: rows of prior_ms (8 col-segments x 128 rows)
    const int row = t >> 3;
    const int seg = t & 7;                     // 16 cols each, float4 loads
    const float4* pr = (const float4*)(prior_ms + (size_t)row * C_DIM + seg * 16);
    float4 q[4];
    #pragma unroll
    for (int i = 0; i < 4; ++i) q[i] = pr[i];
    float rs = 0.f;
    #pragma unroll
    for (int i = 0; i < 4; ++i) rs += q[i].x + q[i].y + q[i].z + q[i].w;
    s_rs8[row][seg] = rs;
    __syncthreads();
    if (t < C_DIM) atomicMax(&s_cmax, s_ccnt[t]);
    if (seg == 0) {
        float tot = 0.f;
        #pragma unroll
        for (int k = 0; k < 8; ++k) tot += s_rs8[row][k];
        s_rs8[row][0] = tot;
        if (tot > 0.f) atomicAdd(&s_nnz, 1);
    }
    __syncthreads();
    const float rstot = s_rs8[row][0];
    if (rstot > 0.f) {
        const float inv = 1.0f / ((float)B * rstot);
        const float* qs = (const float*)q;
        #pragma unroll
        for (int i = 0; i < 16; ++i) {
            float v = qs[i];
            if (v != 0.0f) {
                int slot = atomicAdd(&s_nreg, 1);
                if (slot < MAXREG) {
                    g_reg_cp[slot] = (seg * 16 + i) | (row << 16);
                    g_reg_co[slot] = v * inv;
                }
            }
        }
    }
    __syncthreads();
    if (t == 0) {
        g_nreg      = (s_nreg < MAXREG) ? s_nreg : MAXREG;
        g_colmax    = s_cmax;
        int nnz     = (s_nnz > 0) ? s_nnz : 1;
        g_scale_reg = 4.0f * LN2F / (float)nnz;     // SYMBIOTIC=4, ln2 from log2-domain
    }
}

// ---------------- main kernel: warp per row, float4 per lane, log2 math ---
__global__ void __launch_bounds__(TPB, 4)
main_kernel(const float* __restrict__ logits,
            const float* __restrict__ target,
            const float* __restrict__ weight,
            const float* __restrict__ v1sg, const float* __restrict__ v2sg,
            const float* __restrict__ v1sm, const float* __restrict__ v2sm,
            int B) {
    __shared__ float sh_w[C_DIM];              // weight * ln2 / (B*C)
    __shared__ float sh_sig[3][C_DIM];         // shift * log2e
    __shared__ float sh_sm[3][C_DIM];          // shift * log2e
    __shared__ float sh_ev[WPB][C_DIM];
    __shared__ float sh_a[WPB][C_DIM];
    __shared__ int   s_ci[MAXNZ][C_DIM];       // permuted [k][j*32+l]
    __shared__ float s_cv[MAXNZ][C_DIM];
    __shared__ int   s_rcp[MAXREG];
    __shared__ float s_rco[MAXREG];
    __shared__ float sh_red[TPB];

    const int tid = threadIdx.x;
    const float invBC = LN2F / ((float)B * (float)C_DIM);
    if (tid < C_DIM) {
        sh_w[tid] = weight[tid] * invBC;
        float a1 = v1sg[tid], a2 = v2sg[tid];
        sh_sig[0][tid] = 0.f;
        sh_sig[1][tid] = a1 * LOG2E;
        sh_sig[2][tid] = (a1 - a2) * LOG2E;
        float m1 = v1sm[tid], m2 = v2sm[tid];
        sh_sm[0][tid] = 0.f;
        sh_sm[1][tid] = m1 * LOG2E;
        sh_sm[2][tid] = (m1 - m2) * LOG2E;
        #pragma unroll
        for (int k = 0; k < MAXNZ; ++k) {
            s_ci[k][tid] = g_ci[k][tid];
            s_cv[k][tid] = g_cv[k][tid];
        }
    }
    const int   nreg   = g_nreg;
    const int   colmax = g_colmax;
    const float sreg   = g_scale_reg;
    for (int k = tid; k < nreg; k += TPB) {
        s_rcp[k] = g_reg_cp[k];
        s_rco[k] = g_reg_co[k];
    }
    __syncthreads();

    const int lane   = tid & 31;
    const int w      = tid >> 5;
    const int gwarp  = blockIdx.x * WPB + w;
    const int nwarps = gridDim.x * WPB;

    // clamp bounds in log2 domain
    const float LOGEPS2 = -16.609640474f;      // log2(1e-5)
    const float LOG1ME2 = -1.4427023e-5f;      // log2(1 - 1e-5)

    float acc_bce = 0.f, acc_reg = 0.f;

    const float4 w4 = ((const float4*)sh_w)[lane];
    float wj[4] = {w4.x, w4.y, w4.z, w4.w};

    for (int b = gwarp; b < B; b += nwarps) {
        const float4 tv = ((const float4*)(target + (size_t)b * C_DIM))[lane];
        float tj[4] = {tv.x, tv.y, tv.z, tv.w};

        // ---------- sigmoid experts 0..5 ----------
        #pragma unroll
        for (int e = 0; e < 6; ++e) {
            const float4 x = ((const float4*)(logits + ((size_t)e * B + b) * C_DIM))[lane];
            const int si = (e >= 3) ? (e - 3) : e;
            const float4 sv = ((const float4*)sh_sig[si])[lane];
            float xj[4] = {x.x, x.y, x.z, x.w};
            float sj[4] = {sv.x, sv.y, sv.z, sv.w};
            float areg[4];
            #pragma unroll
            for (int i = 0; i < 4; ++i) {
                float znl = fmaf(xj[i], -LOG2E, sj[i]);     // -z*log2e
                float ex  = exp2f(znl);                     // e^{-z}
                float sp2 = __log2f(1.f + ex);              // softplus(-z)/ln2
                float la  = fminf(fmaxf(-sp2,       LOGEPS2), LOG1ME2);
                float l1a = fminf(fmaxf(znl - sp2,  LOGEPS2), LOG1ME2);
                acc_bce -= wj[i] * fmaf(tj[i], la - l1a, l1a);
                if (e >= 3) {
                    float a = __frcp_rn(1.f + ex);          // sigmoid(z)
                    areg[i] = fminf(fmaxf(a, EPSF), 1.f - EPSF);
                }
            }
            if (e >= 3) {
                __syncwarp();
                ((float4*)sh_a[w])[lane] = make_float4(areg[0], areg[1], areg[2], areg[3]);
                __syncwarp();
                for (int k = lane; k < nreg; k += 32) {
                    int cp = s_rcp[k];
                    float d = sh_a[w][cp & 0xffff] - sh_a[w][cp >> 16];
                    float t2 = __log2f(1.f + exp2f(d * LOG2E));
                    acc_reg = fmaf(s_rco[k], t2, acc_reg);
                }
            }
        }

        // ---------- local-softmax experts 6..11 ----------
        #pragma unroll
        for (int j = 0; j < 6; ++j) {
            const float4 x = ((const float4*)(logits + ((size_t)(6 + j) * B + b) * C_DIM))[lane];
            const int si = (j >= 3) ? (j - 3) : j;
            const float4 sv = ((const float4*)sh_sm[si])[lane];
            float y2[4], ev[4];
            float s = 0.f;
            float xj[4] = {x.x, x.y, x.z, x.w};
            float sj[4] = {sv.x, sv.y, sv.z, sv.w};
            #pragma unroll
            for (int i = 0; i < 4; ++i) {
                y2[i] = fmaf(xj[i], LOG2E, sj[i]);          // (x+shift)*log2e
                ev[i] = exp2f(y2[i]);                       // e^{x+shift}
                s += ev[i];
            }
            #pragma unroll
            for (int o = 16; o > 0; o >>= 1) s += __shfl_xor_sync(0xffffffffu, s, o);
            __syncwarp();
            ((float4*)sh_ev[w])[lane] = make_float4(ev[0], ev[1], ev[2], ev[3]);
            __syncwarp();
            float areg[4];
            #pragma unroll
            for (int i = 0; i < 4; ++i) {
                const int c = 4 * lane + i;
                float corr = 0.f;
                for (int k = 0; k < colmax; ++k) {
                    int   idx = s_ci[k][i * 32 + lane];     // conflict-free
                    float v   = s_cv[k][i * 32 + lane];
                    float e2  = (idx == c) ? ev[i] : sh_ev[w][idx];
                    corr = fmaf(v, e2, corr);
                }
                float dm = s - corr + EPSF;                 // (1-a) numerator
                float dt = dm + ev[i];                      // total denom
                float L2 = __log2f(dt);
                float la  = fminf(fmaxf(y2[i] - L2,         LOGEPS2), LOG1ME2);
                float l1a = fminf(fmaxf(__log2f(dm) - L2,   LOGEPS2), LOG1ME2);
                acc_bce -= wj[i] * fmaf(tj[i], la - l1a, l1a);
                if (j >= 3) {
                    float a = ev[i] * __frcp_rn(dt);
                    areg[i] = fminf(fmaxf(a, EPSF), 1.f - EPSF);
                }
            }
            if (j >= 3) {
                __syncwarp();
                ((float4*)sh_a[w])[lane] = make_float4(areg[0], areg[1], areg[2], areg[3]);
                __syncwarp();
                for (int k = lane; k < nreg; k += 32) {
                    int cp = s_rcp[k];
                    float d = sh_a[w][cp & 0xffff] - sh_a[w][cp >> 16];
                    float t2 = __log2f(1.f + exp2f(d * LOG2E));
                    acc_reg = fmaf(s_rco[k], t2, acc_reg);
                }
            }
        }
    }

    sh_red[tid] = acc_bce + acc_reg * sreg;
    __syncthreads();
    for (int st = TPB / 2; st > 0; st >>= 1) {
        if (tid < st) sh_red[tid] += sh_red[tid + st];
        __syncthreads();
    }
    if (tid == 0) g_partial[blockIdx.x] = sh_red[0];
}

// ---------------- final reduce (fp64 for stability) ----------------------
__global__ void reduce_kernel(float* __restrict__ out, int n) {
    __shared__ double sred[256];
    double s = 0.0;
    for (int i = threadIdx.x; i < n; i += 256) s += (double)g_partial[i];
    sred[threadIdx.x] = s;
    __syncthreads();
    for (int st = 128; st > 0; st >>= 1) {
        if (threadIdx.x < st) sred[threadIdx.x] += sred[threadIdx.x + st];
        __syncthreads();
    }
    if (threadIdx.x == 0) out[0] = (float)sred[0];
}

// ---------------- launch ----------------------
extern "C" void kernel_launch(void* const* d_in, const int* in_sizes, int n_in,
                              void* d_out, int out_size) {
    const float* logits   = (const float*)d_in[0];
    const float* target   = (const float*)d_in[1];
    const float* weight   = (const float*)d_in[2];
    const float* prior_me = (const float*)d_in[3];
    const float* prior_ms = (const float*)d_in[4];
    const float* v1sg     = (const float*)d_in[5];
    const float* v2sg     = (const float*)d_in[6];
    const float* v1sm     = (const float*)d_in[7];
    const float* v2sm     = (const float*)d_in[8];

    const int B = in_sizes[1] / C_DIM;   // target is [B, C]

    setup_kernel<<<1, 1024>>>(prior_me, prior_ms, B);
    main_kernel<<<NBLK, TPB>>>(logits, target, weight, v1sg, v2sg, v1sm, v2sm, B);
    reduce_kernel<<<1, 256>>>((float*)d_out, NBLK);
}

// round 4
// speedup vs baseline: 2.6443x; 1.2876x over previous
#include <cuda_runtime.h>

#define C_DIM   128
#define EPSF    1e-5f
#define MAXNZ   8      // max nonzeros per prior column (actual: 2)
#define MAXREG  512    // max regularizer entries (actual: 112)
#define TPB     256
#define WPB     (TPB/32)
#define NBLK    444    // 3 CTAs/SM * 148 SMs
#define LOG2E   1.4426950408889634f
#define LN2F    0.6931471805599453f

// ---- raw MUFU intrinsics (guaranteed single-instruction) ----
__device__ __forceinline__ float ex2f(float x) {
    float y; asm("ex2.approx.ftz.f32 %0, %1;" : "=f"(y) : "f"(x)); return y;
}
__device__ __forceinline__ float lg2f(float x) {
    float y; asm("lg2.approx.ftz.f32 %0, %1;" : "=f"(y) : "f"(x)); return y;
}
__device__ __forceinline__ float rcpf(float x) {
    float y; asm("rcp.approx.ftz.f32 %0, %1;" : "=f"(y) : "f"(x)); return y;
}

// ---------------- device scratch (no allocations allowed) ----------------
// column-sparse complement of prior_me, PERMUTED layout: [k][(c&3)*32 + (c>>2)]
__device__ int   g_ci[MAXNZ][C_DIM];
__device__ float g_cv[MAXNZ][C_DIM];
__device__ int   g_colmax;
__device__ int   g_nreg;
__device__ float g_scale_reg;         // SYMBIOTIC * ln2 / n_nz
__device__ int   g_reg_cp[MAXREG];    // child | parent<<16
__device__ float g_reg_co[MAXREG];    // val / (B * row_sum)
__device__ float g_partial[4096];

// ---------------- setup: 2 independent blocks (phase A | phase B) --------
__global__ void __launch_bounds__(1024)
setup_kernel(const float* __restrict__ prior_me,
             const float* __restrict__ prior_ms, int B) {
    const int t = threadIdx.x;

    if (blockIdx.x == 0) {
        // ---- phase A: columns of comp = 1 - prior_me
        __shared__ int s_ccnt[C_DIM];
        __shared__ int s_cmax;
        if (t < C_DIM) {
            s_ccnt[t] = 0;
            #pragma unroll
            for (int k = 0; k < MAXNZ; ++k) { g_ci[k][t] = 0; g_cv[k][t] = 0.f; }
        }
        if (t == 0) s_cmax = 0;
        __syncthreads();
        const int col  = t & 127;
        const int rseg = t >> 7;               // 0..7, 16 rows each
        const int pc   = (col & 3) * 32 + (col >> 2);
        float v[16];
        #pragma unroll
        for (int i = 0; i < 16; ++i)
            v[i] = 1.0f - prior_me[(rseg * 16 + i) * C_DIM + col];
        #pragma unroll
        for (int i = 0; i < 16; ++i) {
            if (v[i] != 0.0f) {
                int slot = atomicAdd(&s_ccnt[col], 1);
                if (slot < MAXNZ) {
                    g_ci[slot][pc] = rseg * 16 + i;
                    g_cv[slot][pc] = v[i];
                }
            }
        }
        __syncthreads();
        if (t < C_DIM) atomicMax(&s_cmax, s_ccnt[t]);
        __syncthreads();
        if (t == 0) g_colmax = s_cmax;
    } else {
        // ---- phase B: rows of prior_ms
        __shared__ float s_rs8[C_DIM][8];
        __shared__ int   s_nreg, s_nnz;
        if (t == 0) { s_nreg = 0; s_nnz = 0; }
        __syncthreads();
        const int row = t >> 3;
        const int seg = t & 7;                 // 16 cols each, float4 loads
        const float4* pr = (const float4*)(prior_ms + (size_t)row * C_DIM + seg * 16);
        float4 q[4];
        #pragma unroll
        for (int i = 0; i < 4; ++i) q[i] = pr[i];
        float rs = 0.f;
        #pragma unroll
        for (int i = 0; i < 4; ++i) rs += q[i].x + q[i].y + q[i].z + q[i].w;
        s_rs8[row][seg] = rs;
        __syncthreads();
        if (seg == 0) {
            float tot = 0.f;
            #pragma unroll
            for (int k = 0; k < 8; ++k) tot += s_rs8[row][k];
            s_rs8[row][0] = tot;
            if (tot > 0.f) atomicAdd(&s_nnz, 1);
        }
        __syncthreads();
        const float rstot = s_rs8[row][0];
        if (rstot > 0.f) {
            const float inv = 1.0f / ((float)B * rstot);
            const float* qs = (const float*)q;
            #pragma unroll
            for (int i = 0; i < 16; ++i) {
                float v = qs[i];
                if (v != 0.0f) {
                    int slot = atomicAdd(&s_nreg, 1);
                    if (slot < MAXREG) {
                        g_reg_cp[slot] = (seg * 16 + i) | (row << 16);
                        g_reg_co[slot] = v * inv;
                    }
                }
            }
        }
        __syncthreads();
        if (t == 0) {
            g_nreg      = (s_nreg < MAXREG) ? s_nreg : MAXREG;
            int nnz     = (s_nnz > 0) ? s_nnz : 1;
            g_scale_reg = 4.0f * LN2F / (float)nnz;   // SYMBIOTIC=4, ln2 folded
        }
    }
}

// ---------------- main kernel: warp per row, batched loads, raw MUFU ------
__global__ void __launch_bounds__(TPB, 3)
main_kernel(const float* __restrict__ logits,
            const float* __restrict__ target,
            const float* __restrict__ weight,
            const float* __restrict__ v1sg, const float* __restrict__ v2sg,
            const float* __restrict__ v1sm, const float* __restrict__ v2sm,
            int B) {
    __shared__ float sh_w[C_DIM];              // weight * ln2 / (B*C)
    __shared__ float sh_sig[3][C_DIM];         // shift * log2e
    __shared__ float sh_sm[3][C_DIM];          // shift * log2e
    __shared__ float sh_ev[WPB][C_DIM];
    __shared__ float sh_a[WPB][C_DIM];
    __shared__ int   s_ci[MAXNZ][C_DIM];       // permuted [k][j*32+l]
    __shared__ float s_cv[MAXNZ][C_DIM];
    __shared__ int   s_rcp[MAXREG];
    __shared__ float s_rco[MAXREG];
    __shared__ float sh_red[TPB];

    const int tid = threadIdx.x;
    const float invBC = LN2F / ((float)B * (float)C_DIM);
    if (tid < C_DIM) {
        sh_w[tid] = weight[tid] * invBC;
        float a1 = v1sg[tid], a2 = v2sg[tid];
        sh_sig[0][tid] = 0.f;
        sh_sig[1][tid] = a1 * LOG2E;
        sh_sig[2][tid] = (a1 - a2) * LOG2E;
        float m1 = v1sm[tid], m2 = v2sm[tid];
        sh_sm[0][tid] = 0.f;
        sh_sm[1][tid] = m1 * LOG2E;
        sh_sm[2][tid] = (m1 - m2) * LOG2E;
        #pragma unroll
        for (int k = 0; k < MAXNZ; ++k) {
            s_ci[k][tid] = g_ci[k][tid];
            s_cv[k][tid] = g_cv[k][tid];
        }
    }
    const int   nreg   = g_nreg;
    const int   colmax = g_colmax;
    const float sreg   = g_scale_reg;
    for (int k = tid; k < nreg; k += TPB) {
        s_rcp[k] = g_reg_cp[k];
        s_rco[k] = g_reg_co[k];
    }
    __syncthreads();

    const int lane   = tid & 31;
    const int w      = tid >> 5;
    const int gwarp  = blockIdx.x * WPB + w;
    const int nwarps = gridDim.x * WPB;

    const float LOGEPS2 = -16.609640474f;      // log2(1e-5)
    const float LOG1ME2 = -1.4427023e-5f;      // log2(1 - 1e-5)

    float acc_bce = 0.f, acc_reg = 0.f;

    const float4 w4 = ((const float4*)sh_w)[lane];
    float wj[4] = {w4.x, w4.y, w4.z, w4.w};

    for (int b = gwarp; b < B; b += nwarps) {
        // -------- batch ALL row loads first: MLP = 13 --------
        const float4 tv = __ldg((const float4*)(target + (size_t)b * C_DIM) + lane);
        float4 xs[6], xm[6];
        #pragma unroll
        for (int e = 0; e < 6; ++e)
            xs[e] = __ldg((const float4*)(logits + ((size_t)e * B + b) * C_DIM) + lane);
        #pragma unroll
        for (int e = 0; e < 6; ++e)
            xm[e] = __ldg((const float4*)(logits + ((size_t)(6 + e) * B + b) * C_DIM) + lane);
        float tj[4] = {tv.x, tv.y, tv.z, tv.w};

        // ---------- sigmoid experts 0..5 ----------
        #pragma unroll
        for (int e = 0; e < 6; ++e) {
            const int si = (e >= 3) ? (e - 3) : e;
            const float4 sv = ((const float4*)sh_sig[si])[lane];
            float xj[4] = {xs[e].x, xs[e].y, xs[e].z, xs[e].w};
            float sj[4] = {sv.x, sv.y, sv.z, sv.w};
            float areg[4];
            #pragma unroll
            for (int i = 0; i < 4; ++i) {
                float znl = fmaf(xj[i], -LOG2E, sj[i]);     // -z*log2e
                float ex  = ex2f(znl);                      // e^{-z}
                float sp2 = lg2f(1.f + ex);                 // softplus(-z)/ln2
                float la  = fminf(fmaxf(-sp2,       LOGEPS2), LOG1ME2);
                float l1a = fminf(fmaxf(znl - sp2,  LOGEPS2), LOG1ME2);
                acc_bce -= wj[i] * fmaf(tj[i], la - l1a, l1a);
                if (e >= 3) {
                    float a = rcpf(1.f + ex);               // sigmoid(z)
                    areg[i] = fminf(fmaxf(a, EPSF), 1.f - EPSF);
                }
            }
            if (e >= 3) {
                __syncwarp();
                ((float4*)sh_a[w])[lane] = make_float4(areg[0], areg[1], areg[2], areg[3]);
                __syncwarp();
                for (int k = lane; k < nreg; k += 32) {
                    int cp = s_rcp[k];
                    float d = sh_a[w][cp & 0xffff] - sh_a[w][cp >> 16];
                    float t2 = lg2f(1.f + ex2f(d * LOG2E));
                    acc_reg = fmaf(s_rco[k], t2, acc_reg);
                }
            }
        }

        // ---------- local-softmax experts 6..11 ----------
        #pragma unroll
        for (int j = 0; j < 6; ++j) {
            const int si = (j >= 3) ? (j - 3) : j;
            const float4 sv = ((const float4*)sh_sm[si])[lane];
            float y2[4], ev[4];
            float s = 0.f;
            float xj[4] = {xm[j].x, xm[j].y, xm[j].z, xm[j].w};
            float sj[4] = {sv.x, sv.y, sv.z, sv.w};
            #pragma unroll
            for (int i = 0; i < 4; ++i) {
                y2[i] = fmaf(xj[i], LOG2E, sj[i]);          // (x+shift)*log2e
                ev[i] = ex2f(y2[i]);                        // e^{x+shift}
                s += ev[i];
            }
            #pragma unroll
            for (int o = 16; o > 0; o >>= 1) s += __shfl_xor_sync(0xffffffffu, s, o);
            __syncwarp();
            ((float4*)sh_ev[w])[lane] = make_float4(ev[0], ev[1], ev[2], ev[3]);
            __syncwarp();
            float areg[4];
            #pragma unroll
            for (int i = 0; i < 4; ++i) {
                const int c = 4 * lane + i;
                float corr = 0.f;
                for (int k = 0; k < colmax; ++k) {
                    int   idx = s_ci[k][i * 32 + lane];     // conflict-free
                    float v   = s_cv[k][i * 32 + lane];
                    float e2  = (idx == c) ? ev[i] : sh_ev[w][idx];
                    corr = fmaf(v, e2, corr);
                }
                float dm = s - corr + EPSF;                 // (1-a) numerator
                float dt = dm + ev[i];                      // total denom
                float L2 = lg2f(dt);
                float la  = fminf(fmaxf(y2[i] - L2,       LOGEPS2), LOG1ME2);
                float l1a = fminf(fmaxf(lg2f(dm) - L2,    LOGEPS2), LOG1ME2);
                acc_bce -= wj[i] * fmaf(tj[i], la - l1a, l1a);
                if (j >= 3) {
                    float a = ev[i] * rcpf(dt);
                    areg[i] = fminf(fmaxf(a, EPSF), 1.f - EPSF);
                }
            }
            if (j >= 3) {
                __syncwarp();
                ((float4*)sh_a[w])[lane] = make_float4(areg[0], areg[1], areg[2], areg[3]);
                __syncwarp();
                for (int k = lane; k < nreg; k += 32) {
                    int cp = s_rcp[k];
                    float d = sh_a[w][cp & 0xffff] - sh_a[w][cp >> 16];
                    float t2 = lg2f(1.f + ex2f(d * LOG2E));
                    acc_reg = fmaf(s_rco[k], t2, acc_reg);
                }
            }
        }
    }

    sh_red[tid] = acc_bce + acc_reg * sreg;
    __syncthreads();
    for (int st = TPB / 2; st > 0; st >>= 1) {
        if (tid < st) sh_red[tid] += sh_red[tid + st];
        __syncthreads();
    }
    if (tid == 0) g_partial[blockIdx.x] = sh_red[0];
}

// ---------------- final reduce (fp64 for stability) ----------------------
__global__ void reduce_kernel(float* __restrict__ out, int n) {
    __shared__ double sred[256];
    double s = 0.0;
    for (int i = threadIdx.x; i < n; i += 256) s += (double)g_partial[i];
    sred[threadIdx.x] = s;
    __syncthreads();
    for (int st = 128; st > 0; st >>= 1) {
        if (threadIdx.x < st) sred[threadIdx.x] += sred[threadIdx.x + st];
        __syncthreads();
    }
    if (threadIdx.x == 0) out[0] = (float)sred[0];
}

// ---------------- launch ----------------------
extern "C" void kernel_launch(void* const* d_in, const int* in_sizes, int n_in,
                              void* d_out, int out_size) {
    const float* logits   = (const float*)d_in[0];
    const float* target   = (const float*)d_in[1];
    const float* weight   = (const float*)d_in[2];
    const float* prior_me = (const float*)d_in[3];
    const float* prior_ms = (const float*)d_in[4];
    const float* v1sg     = (const float*)d_in[5];
    const float* v2sg     = (const float*)d_in[6];
    const float* v1sm     = (const float*)d_in[7];
    const float* v2sm     = (const float*)d_in[8];

    const int B = in_sizes[1] / C_DIM;   // target is [B, C]

    setup_kernel<<<2, 1024>>>(prior_me, prior_ms, B);
    main_kernel<<<NBLK, TPB>>>(logits, target, weight, v1sg, v2sg, v1sm, v2sm, B);
    reduce_kernel<<<1, 256>>>((float*)d_out, NBLK);
}